// round 15
// baseline (speedup 1.0000x reference)
#include <cuda_runtime.h>
#include <cuda_fp16.h>
#include <cstdint>
#include <math.h>

#define B_  2
#define T_  2048
#define D_  1024
#define H_  16
#define DH  64
#define M_  (B_*T_)
#define NEG_INF_F (-1.0e9f)
#define QSC 0.18033688011112042f   // 0.125 * log2(e)

// Scratch (allocation-free rule: __device__ globals)
__device__ __half g_qh[(size_t)B_*H_*T_*DH];
__device__ __half g_kh[(size_t)B_*H_*T_*DH];
__device__ __half g_vh[(size_t)B_*H_*T_*DH];
__device__ __half g_attn[(size_t)M_*D_];
__device__ __half g_xh[(size_t)M_*D_];
__device__ __half g_wh[(size_t)4*D_*D_];

// ===========================================================================
// helpers
// ===========================================================================
__device__ __forceinline__ unsigned packh2(float lo, float hi) {
    __half2 h = __floats2half2_rn(lo, hi);
    return *(unsigned*)&h;
}
__device__ __forceinline__ float ex2(float x) {
    float y;
    asm("ex2.approx.ftz.f32 %0, %1;" : "=f"(y) : "f"(x));
    return y;
}
// packed half2 exp2: one MUFU op for two values; result is the P fragment
__device__ __forceinline__ unsigned h2ex2(float a, float b) {
    __half2 h = __floats2half2_rn(a, b);
    unsigned r;
    asm("ex2.approx.f16x2 %0, %1;" : "=r"(r) : "r"(*(unsigned*)&h));
    return r;
}
__device__ __forceinline__ uint32_t smaddr(const void* p) {
    return (uint32_t)__cvta_generic_to_shared(p);
}
__device__ __forceinline__ void mma_f16(float* c, const unsigned* a, const unsigned* b) {
    asm volatile(
        "mma.sync.aligned.m16n8k16.row.col.f32.f16.f16.f32 "
        "{%0,%1,%2,%3}, {%4,%5,%6,%7}, {%8,%9}, {%0,%1,%2,%3};\n"
        : "+f"(c[0]), "+f"(c[1]), "+f"(c[2]), "+f"(c[3])
        : "r"(a[0]), "r"(a[1]), "r"(a[2]), "r"(a[3]),
          "r"(b[0]), "r"(b[1]));
}
__device__ __forceinline__ void ldsm_x4(unsigned* r, uint32_t a) {
    asm volatile("ldmatrix.sync.aligned.m8n8.x4.shared.b16 {%0,%1,%2,%3}, [%4];"
        : "=r"(r[0]), "=r"(r[1]), "=r"(r[2]), "=r"(r[3]) : "r"(a));
}
__device__ __forceinline__ void ldsm_x2(unsigned* r, uint32_t a) {
    asm volatile("ldmatrix.sync.aligned.m8n8.x2.shared.b16 {%0,%1}, [%2];"
        : "=r"(r[0]), "=r"(r[1]) : "r"(a));
}
__device__ __forceinline__ void ldsm_x4t(unsigned* r, uint32_t a) {
    asm volatile("ldmatrix.sync.aligned.m8n8.x4.trans.shared.b16 {%0,%1,%2,%3}, [%4];"
        : "=r"(r[0]), "=r"(r[1]), "=r"(r[2]), "=r"(r[3]) : "r"(a));
}
__device__ __forceinline__ void cpasync16(uint32_t dst, const void* src) {
    asm volatile("cp.async.cg.shared.global [%0], [%1], 16;" :: "r"(dst), "l"(src));
}

// ===========================================================================
// fp32 -> fp16 conversion for x (1M float4) and 4 weight matrices (256K each)
// ===========================================================================
__global__ __launch_bounds__(256) void convert_all(
    const float* __restrict__ x,
    const float* __restrict__ wq, const float* __restrict__ wk,
    const float* __restrict__ wv, const float* __restrict__ wo,
    __half* __restrict__ xh, __half* __restrict__ wh)
{
    const int idx = blockIdx.x * 256 + threadIdx.x;
    const float* src;
    __half* dst;
    if (idx < (1 << 20)) {
        src = x + (size_t)idx * 4;
        dst = xh + (size_t)idx * 4;
    } else {
        int j = idx - (1 << 20);
        int w = j >> 18;
        int off = j & ((1 << 18) - 1);
        const float* ws = (w == 0) ? wq : (w == 1) ? wk : (w == 2) ? wv : wo;
        src = ws + (size_t)off * 4;
        dst = wh + ((size_t)w << 20) + (size_t)off * 4;
    }
    float4 v = *(const float4*)src;
    uint2 u;
    u.x = packh2(v.x, v.y);
    u.y = packh2(v.z, v.w);
    *(uint2*)dst = u;
}

// ===========================================================================
// fp16 tensor-core GEMM (round-14 proven): 128x128 tile, BK=32, 3-stage
// cp.async pipeline, swizzled 64B rows, kk=0 ldsm hoisted, ONE sync/K-tile.
// 256 threads, 2 CTAs/SM.
// ===========================================================================
#define GBUF 8192
#define GSTG3 3

__global__ __launch_bounds__(256, 2) void mma_gemm_f16(
    const __half* __restrict__ A, const __half* __restrict__ Wbase,
    const float* __restrict__ bb0, void* __restrict__ C0,
    const float* __restrict__ bb1, void* __restrict__ C1,
    const float* __restrict__ bb2, void* __restrict__ C2,
    int mode, float scale0)
{
    const int z = blockIdx.z;
    const __half* W   = Wbase + ((size_t)z << 20);
    const float* bias = (z == 0) ? bb0 : (z == 1) ? bb1 : bb2;
    void* C           = (z == 0) ? C0  : (z == 1) ? C1  : C2;
    const float sc    = (z == 0) ? scale0 : 1.0f;

    __shared__ unsigned char gsm[2 * GSTG3 * GBUF];   // 48 KB

    const int tid  = threadIdx.x;
    const int warp = tid >> 5, lane = tid & 31;
    const int g = lane >> 2, l = lane & 3;
    const int wm = (warp >> 2) * 64;
    const int wn = (warp & 3) * 32;
    const int m0 = blockIdx.y * 128;
    const int n0 = blockIdx.x * 128;

    const int crow = tid >> 2;
    const int cch  = (tid & 3) * 8;
    const int sst  = (tid >> 3) & 3;
    const int cdst = crow * 64 + (((tid & 3) ^ sst) * 16);

    const int a_hi  = lane >> 4;
    const int sa    = ((lane & 15) >> 1) & 3;
    const int a_row = (wm + (lane & 15)) * 64;
    const int ac0   = ((0 + a_hi) ^ sa) * 16;
    const int ac1   = ((2 + a_hi) ^ sa) * 16;
    const int b_hi  = (lane >> 3) & 1;
    const int sb    = ((lane & 7) >> 1) & 3;
    const int b_row = (wn + (lane & 7)) * 64;
    const int bc0   = ((0 + b_hi) ^ sb) * 16;
    const int bc1   = ((2 + b_hi) ^ sb) * 16;

    const uint32_t sA0 = smaddr(gsm);
    const uint32_t sW0 = sA0 + GSTG3 * GBUF;

    const __half* Abase = A + (size_t)(m0 + crow) * D_ + cch;
    const __half* Wrow  = W + (size_t)(n0 + crow) * D_ + cch;

    float acc[4][4][4];
#pragma unroll
    for (int mi = 0; mi < 4; mi++)
#pragma unroll
        for (int ni = 0; ni < 4; ni++)
#pragma unroll
            for (int e = 0; e < 4; e++) acc[mi][ni][e] = 0.0f;

#pragma unroll
    for (int s = 0; s < 2; s++) {
        const __half* as = Abase + s * 32;
        const __half* ws = Wrow  + s * 32;
        cpasync16(sA0 + s * GBUF + cdst, as);
        cpasync16(sW0 + s * GBUF + cdst, ws);
        cpasync16(sA0 + s * GBUF + cdst + 4096, as + 64 * D_);
        cpasync16(sW0 + s * GBUF + cdst + 4096, ws + 64 * D_);
        asm volatile("cp.async.commit_group;");
    }

    int bc = 0;
    int nb = 2;
    for (int kt = 0; kt < 32; kt++) {
        asm volatile("cp.async.wait_group 1;");
        __syncthreads();

        const uint32_t aB = sA0 + bc * GBUF + a_row;
        const uint32_t bB = sW0 + bc * GBUF + b_row;

        unsigned af[4][4], bf[4][2];
#pragma unroll
        for (int mi = 0; mi < 4; mi++)
            ldsm_x4(af[mi], aB + mi * 1024 + ac0);
#pragma unroll
        for (int ni = 0; ni < 4; ni++)
            ldsm_x2(bf[ni], bB + ni * 512 + bc0);

        {
            const int nt = (kt + 2 < 32) ? (kt + 2) : 31;
            const __half* as = Abase + nt * 32;
            const __half* ws = Wrow  + nt * 32;
            cpasync16(sA0 + nb * GBUF + cdst, as);
            cpasync16(sW0 + nb * GBUF + cdst, ws);
            cpasync16(sA0 + nb * GBUF + cdst + 4096, as + 64 * D_);
            cpasync16(sW0 + nb * GBUF + cdst + 4096, ws + 64 * D_);
            asm volatile("cp.async.commit_group;");
        }

#pragma unroll
        for (int mi = 0; mi < 4; mi++)
#pragma unroll
            for (int ni = 0; ni < 4; ni++)
                mma_f16(acc[mi][ni], af[mi], bf[ni]);

#pragma unroll
        for (int mi = 0; mi < 4; mi++)
            ldsm_x4(af[mi], aB + mi * 1024 + ac1);
#pragma unroll
        for (int ni = 0; ni < 4; ni++)
            ldsm_x2(bf[ni], bB + ni * 512 + bc1);
#pragma unroll
        for (int mi = 0; mi < 4; mi++)
#pragma unroll
            for (int ni = 0; ni < 4; ni++)
                mma_f16(acc[mi][ni], af[mi], bf[ni]);

        bc++; if (bc == 3) bc = 0;
        nb++; if (nb == 3) nb = 0;
    }

    // epilogue
#pragma unroll
    for (int ni = 0; ni < 4; ni++) {
        int n = n0 + wn + ni * 8 + 2 * l;
        float bv0 = __ldg(bias + n);
        float bv1 = __ldg(bias + n + 1);
#pragma unroll
        for (int mi = 0; mi < 4; mi++) {
            int m = m0 + wm + mi * 16 + g;
#pragma unroll
            for (int half_ = 0; half_ < 2; half_++) {
                int mm = m + half_ * 8;
                float v0 = acc[mi][ni][half_ * 2 + 0] + bv0;
                float v1 = acc[mi][ni][half_ * 2 + 1] + bv1;
                if (mode == 0) {
                    float2 v; v.x = v0; v.y = v1;
                    *(float2*)((float*)C + (size_t)mm * D_ + n) = v;
                } else {
                    int bb = mm >> 11;
                    int t  = mm & (T_ - 1);
                    int hh = n >> 6;
                    int d  = n & (DH - 1);
                    unsigned hv = packh2(v0 * sc, v1 * sc);
                    *(unsigned*)((__half*)C + (((size_t)(bb * H_ + hh)) * T_ + t) * DH + d) = hv;
                }
            }
        }
    }
}

// ===========================================================================
// fp16 flash attention: BM=256 (16 warps, 512 threads), BN=64, dh=64.
// 2-stage cp.async pipeline, ONE sync/tile, x4 / x4.trans pair loads,
// all-ones mask fast path. Softmax exp via ex2.approx.f16x2 (16 MUFU ops
// per tile instead of 32; output doubles as the packed P fragment).
// Output fp16 [B,T,D].
// ===========================================================================
#define FBM 256
#define FBN 64
#define ATB (FBN*72*2)

__global__ __launch_bounds__(512, 1) void attn_f16(
    const __half* __restrict__ Qh, const __half* __restrict__ Kh,
    const __half* __restrict__ Vh, const int* __restrict__ mask,
    __half* __restrict__ O)
{
    __shared__ __half Ks[2][FBN][72];
    __shared__ __half Vs[2][FBN][72];
    __shared__ int    Mall[T_];
    __shared__ int    Mflag[T_/FBN];

    const int bh = blockIdx.y;
    const int b  = bh >> 4;
    const int h  = bh & (H_ - 1);
    const int tid  = threadIdx.x;
    const int warp = tid >> 5, lane = tid & 31;
    const int g = lane >> 2, l = lane & 3;
    const int mrow0 = blockIdx.x * FBM + warp * 16;

    const __half* kb0 = Kh + (size_t)bh * T_ * DH;
    const __half* vb0 = Vh + (size_t)bh * T_ * DH;
    const uint32_t ks0 = smaddr(&Ks[0][0][0]);
    const uint32_t vs0 = smaddr(&Vs[0][0][0]);

    const int crow0 = tid >> 3;
    const int cc8   = (tid & 7) * 8;
    const int cdst  = crow0 * 144 + (tid & 7) * 16;

    {
        cpasync16(ks0 + cdst, kb0 + (size_t)crow0 * DH + cc8);
        cpasync16(vs0 + cdst, vb0 + (size_t)crow0 * DH + cc8);
        asm volatile("cp.async.commit_group;");
    }

    for (int i = tid; i < T_; i += 512) Mall[i] = mask[b * T_ + i];
    __syncthreads();
    if (tid < T_/FBN) {
        int f = 1;
        for (int j = 0; j < FBN; j++) f &= Mall[tid * FBN + j];
        Mflag[tid] = f;
    }

    unsigned qf[4][4];
    {
        const __half* qb = Qh + ((size_t)bh * T_ + mrow0) * DH;
#pragma unroll
        for (int kt = 0; kt < 4; kt++) {
            qf[kt][0] = *(const unsigned*)(qb + (size_t)g       * DH + kt*16 + 2*l);
            qf[kt][1] = *(const unsigned*)(qb + (size_t)(g + 8) * DH + kt*16 + 2*l);
            qf[kt][2] = *(const unsigned*)(qb + (size_t)g       * DH + kt*16 + 2*l + 8);
            qf[kt][3] = *(const unsigned*)(qb + (size_t)(g + 8) * DH + kt*16 + 2*l + 8);
        }
    }

    float oa[8][4];
#pragma unroll
    for (int ni = 0; ni < 8; ni++)
#pragma unroll
        for (int e = 0; e < 4; e++) oa[ni][e] = 0.0f;
    float m0 = -INFINITY, m1 = -INFINITY;
    float l0 = 0.0f, l1 = 0.0f;

    const int q4 = lane >> 3;
    const int sq_base = ((lane & 7) + (q4 >> 1) * 8) * 144 + (q4 & 1) * 16;
    const int pv_base = ((q4 & 1) * 8 + (lane & 7)) * 144 + (q4 >> 1) * 16;

    for (int t = 0; t < 32; t++) {
        const int buf = t & 1;
        asm volatile("cp.async.wait_group 0;");
        __syncthreads();

        if (t < 31) {
            const int nb2 = buf ^ 1;
            cpasync16(ks0 + nb2 * ATB + cdst, kb0 + (size_t)((t + 1) * FBN + crow0) * DH + cc8);
            cpasync16(vs0 + nb2 * ATB + cdst, vb0 + (size_t)((t + 1) * FBN + crow0) * DH + cc8);
            asm volatile("cp.async.commit_group;");
        }

        // S = Q K^T
        float sa[8][4];
#pragma unroll
        for (int ni = 0; ni < 8; ni++)
#pragma unroll
            for (int e = 0; e < 4; e++) sa[ni][e] = 0.0f;
        const uint32_t kbase = ks0 + buf * ATB + sq_base;
#pragma unroll
        for (int kt = 0; kt < 4; kt++) {
#pragma unroll
            for (int np = 0; np < 4; np++) {
                unsigned b4[4];
                ldsm_x4(b4, kbase + np * 2304 + kt * 32);
                mma_f16(sa[2*np],     qf[kt], b4);
                mma_f16(sa[2*np + 1], qf[kt], b4 + 2);
            }
        }

        // mask (skipped when the whole 64-block is unmasked)
        if (!Mflag[t]) {
            const int mb = t * FBN;
#pragma unroll
            for (int ni = 0; ni < 8; ni++) {
                int c0m = Mall[mb + ni*8 + 2*l];
                int c1m = Mall[mb + ni*8 + 2*l + 1];
                if (!c0m) { sa[ni][0] = NEG_INF_F; sa[ni][2] = NEG_INF_F; }
                if (!c1m) { sa[ni][1] = NEG_INF_F; sa[ni][3] = NEG_INF_F; }
            }
        }

        float rm0 = -INFINITY, rm1 = -INFINITY;
#pragma unroll
        for (int ni = 0; ni < 8; ni++) {
            rm0 = fmaxf(rm0, fmaxf(sa[ni][0], sa[ni][1]));
            rm1 = fmaxf(rm1, fmaxf(sa[ni][2], sa[ni][3]));
        }
        rm0 = fmaxf(rm0, __shfl_xor_sync(0xffffffffu, rm0, 1));
        rm0 = fmaxf(rm0, __shfl_xor_sync(0xffffffffu, rm0, 2));
        rm1 = fmaxf(rm1, __shfl_xor_sync(0xffffffffu, rm1, 1));
        rm1 = fmaxf(rm1, __shfl_xor_sync(0xffffffffu, rm1, 2));
        float mn0 = fmaxf(m0, rm0);
        float mn1 = fmaxf(m1, rm1);
        float cr0 = ex2(m0 - mn0);
        float cr1 = ex2(m1 - mn1);

        // exp via packed f16x2 MUFU; result IS the P fragment
        unsigned pk[8][2];
        float ts0 = 0.0f, ts1 = 0.0f;
#pragma unroll
        for (int ni = 0; ni < 8; ni++) {
            unsigned p0 = h2ex2(sa[ni][0] - mn0, sa[ni][1] - mn0);
            unsigned p1 = h2ex2(sa[ni][2] - mn1, sa[ni][3] - mn1);
            pk[ni][0] = p0;
            pk[ni][1] = p1;
            float2 f0 = __half22float2(*(__half2*)&p0);
            float2 f1 = __half22float2(*(__half2*)&p1);
            ts0 += f0.x + f0.y;
            ts1 += f1.x + f1.y;
        }
        l0 = l0 * cr0 + ts0;
        l1 = l1 * cr1 + ts1;
#pragma unroll
        for (int ni = 0; ni < 8; ni++) {
            oa[ni][0] *= cr0; oa[ni][1] *= cr0;
            oa[ni][2] *= cr1; oa[ni][3] *= cr1;
        }
        m0 = mn0; m1 = mn1;

        // O += P V
        const uint32_t vbase = vs0 + buf * ATB + pv_base;
#pragma unroll
        for (int kt2 = 0; kt2 < 4; kt2++) {
            unsigned pa[4];
            pa[0] = pk[2*kt2][0];
            pa[1] = pk[2*kt2][1];
            pa[2] = pk[2*kt2 + 1][0];
            pa[3] = pk[2*kt2 + 1][1];
#pragma unroll
            for (int np = 0; np < 4; np++) {
                unsigned b4[4];
                ldsm_x4t(b4, vbase + kt2 * 2304 + np * 32);
                mma_f16(oa[2*np],     pa, b4);
                mma_f16(oa[2*np + 1], pa, b4 + 2);
            }
        }
    }

    l0 += __shfl_xor_sync(0xffffffffu, l0, 1);
    l0 += __shfl_xor_sync(0xffffffffu, l0, 2);
    l1 += __shfl_xor_sync(0xffffffffu, l1, 1);
    l1 += __shfl_xor_sync(0xffffffffu, l1, 2);
    float i0 = 1.0f / l0;
    float i1 = 1.0f / l1;

    __half* ob = O + ((size_t)(b * T_ + mrow0)) * D_ + h * DH;
#pragma unroll
    for (int ni = 0; ni < 8; ni++) {
        unsigned v0 = packh2(oa[ni][0] * i0, oa[ni][1] * i0);
        unsigned v1 = packh2(oa[ni][2] * i1, oa[ni][3] * i1);
        *(unsigned*)(ob + (size_t)g       * D_ + ni*8 + 2*l) = v0;
        *(unsigned*)(ob + (size_t)(g + 8) * D_ + ni*8 + 2*l) = v1;
    }
}

// ===========================================================================
extern "C" void kernel_launch(void* const* d_in, const int* in_sizes, int n_in,
                              void* d_out, int out_size)
{
    (void)in_sizes; (void)n_in; (void)out_size;
    const float* x    = (const float*)d_in[0];
    const int*   mask = (const int*)  d_in[1];
    const float* Wq   = (const float*)d_in[2];
    const float* bq   = (const float*)d_in[3];
    const float* Wk   = (const float*)d_in[4];
    const float* bk   = (const float*)d_in[5];
    const float* Wv   = (const float*)d_in[6];
    const float* bv   = (const float*)d_in[7];
    const float* Wo   = (const float*)d_in[8];
    const float* bo   = (const float*)d_in[9];
    float* out = (float*)d_out;

    __half *q, *k, *v, *attn, *xh, *wh;
    cudaGetSymbolAddress((void**)&q,    g_qh);
    cudaGetSymbolAddress((void**)&k,    g_kh);
    cudaGetSymbolAddress((void**)&v,    g_vh);
    cudaGetSymbolAddress((void**)&attn, g_attn);
    cudaGetSymbolAddress((void**)&xh,   g_xh);
    cudaGetSymbolAddress((void**)&wh,   g_wh);

    convert_all<<<8192, 256>>>(x, Wq, Wk, Wv, Wo, xh, wh);

    mma_gemm_f16<<<dim3(D_/128, M_/128, 3), 256>>>(
        xh, wh, bq, q, bk, k, bv, v, 1, QSC);

    attn_f16<<<dim3(T_/FBM, B_*H_), 512>>>(q, k, v, mask, attn);

    mma_gemm_f16<<<dim3(D_/128, M_/128, 1), 256>>>(
        attn, wh + ((size_t)3 << 20), bo, out, bo, out, bo, out, 0, 1.0f);
}

// round 16
// speedup vs baseline: 1.0319x; 1.0319x over previous
#include <cuda_runtime.h>
#include <cuda_fp16.h>
#include <cstdint>
#include <math.h>

#define B_  2
#define T_  2048
#define D_  1024
#define H_  16
#define DH  64
#define M_  (B_*T_)
#define NEG_INF_F (-1.0e9f)
#define QSC 0.18033688011112042f   // 0.125 * log2(e)

// Scratch (allocation-free rule: __device__ globals)
__device__ __half g_qh[(size_t)B_*H_*T_*DH];
__device__ __half g_kh[(size_t)B_*H_*T_*DH];
__device__ __half g_vh[(size_t)B_*H_*T_*DH];
__device__ __half g_attn[(size_t)M_*D_];
__device__ __half g_xh[(size_t)M_*D_];
__device__ __half g_wh[(size_t)4*D_*D_];

// ===========================================================================
// helpers
// ===========================================================================
__device__ __forceinline__ unsigned packh2(float lo, float hi) {
    __half2 h = __floats2half2_rn(lo, hi);
    return *(unsigned*)&h;
}
__device__ __forceinline__ float ex2(float x) {
    float y;
    asm("ex2.approx.ftz.f32 %0, %1;" : "=f"(y) : "f"(x));
    return y;
}
// packed half2 exp2: one MUFU op for two values; result is the P fragment
__device__ __forceinline__ unsigned h2ex2(float a, float b) {
    __half2 h = __floats2half2_rn(a, b);
    unsigned r;
    asm("ex2.approx.f16x2 %0, %1;" : "=r"(r) : "r"(*(unsigned*)&h));
    return r;
}
__device__ __forceinline__ uint32_t smaddr(const void* p) {
    return (uint32_t)__cvta_generic_to_shared(p);
}
__device__ __forceinline__ void mma_f16(float* c, const unsigned* a, const unsigned* b) {
    asm volatile(
        "mma.sync.aligned.m16n8k16.row.col.f32.f16.f16.f32 "
        "{%0,%1,%2,%3}, {%4,%5,%6,%7}, {%8,%9}, {%0,%1,%2,%3};\n"
        : "+f"(c[0]), "+f"(c[1]), "+f"(c[2]), "+f"(c[3])
        : "r"(a[0]), "r"(a[1]), "r"(a[2]), "r"(a[3]),
          "r"(b[0]), "r"(b[1]));
}
__device__ __forceinline__ void ldsm_x4(unsigned* r, uint32_t a) {
    asm volatile("ldmatrix.sync.aligned.m8n8.x4.shared.b16 {%0,%1,%2,%3}, [%4];"
        : "=r"(r[0]), "=r"(r[1]), "=r"(r[2]), "=r"(r[3]) : "r"(a));
}
__device__ __forceinline__ void ldsm_x2(unsigned* r, uint32_t a) {
    asm volatile("ldmatrix.sync.aligned.m8n8.x2.shared.b16 {%0,%1}, [%2];"
        : "=r"(r[0]), "=r"(r[1]) : "r"(a));
}
__device__ __forceinline__ void ldsm_x4t(unsigned* r, uint32_t a) {
    asm volatile("ldmatrix.sync.aligned.m8n8.x4.trans.shared.b16 {%0,%1,%2,%3}, [%4];"
        : "=r"(r[0]), "=r"(r[1]), "=r"(r[2]), "=r"(r[3]) : "r"(a));
}
__device__ __forceinline__ void cpasync16(uint32_t dst, const void* src) {
    asm volatile("cp.async.cg.shared.global [%0], [%1], 16;" :: "r"(dst), "l"(src));
}

// ===========================================================================
// fp32 -> fp16 conversion for x (1M float4) and 4 weight matrices (256K each)
// ===========================================================================
__global__ __launch_bounds__(256) void convert_all(
    const float* __restrict__ x,
    const float* __restrict__ wq, const float* __restrict__ wk,
    const float* __restrict__ wv, const float* __restrict__ wo,
    __half* __restrict__ xh, __half* __restrict__ wh)
{
    const int idx = blockIdx.x * 256 + threadIdx.x;
    const float* src;
    __half* dst;
    if (idx < (1 << 20)) {
        src = x + (size_t)idx * 4;
        dst = xh + (size_t)idx * 4;
    } else {
        int j = idx - (1 << 20);
        int w = j >> 18;
        int off = j & ((1 << 18) - 1);
        const float* ws = (w == 0) ? wq : (w == 1) ? wk : (w == 2) ? wv : wo;
        src = ws + (size_t)off * 4;
        dst = wh + ((size_t)w << 20) + (size_t)off * 4;
    }
    float4 v = *(const float4*)src;
    uint2 u;
    u.x = packh2(v.x, v.y);
    u.y = packh2(v.z, v.w);
    *(uint2*)dst = u;
}

// ===========================================================================
// fp16 tensor-core GEMM (round-14 proven): 128x128 tile, BK=32, 3-stage
// cp.async pipeline, swizzled 64B rows, kk=0 ldsm hoisted, ONE sync/K-tile.
// 256 threads, 2 CTAs/SM.
// ===========================================================================
#define GBUF 8192
#define GSTG3 3

__global__ __launch_bounds__(256, 2) void mma_gemm_f16(
    const __half* __restrict__ A, const __half* __restrict__ Wbase,
    const float* __restrict__ bb0, void* __restrict__ C0,
    const float* __restrict__ bb1, void* __restrict__ C1,
    const float* __restrict__ bb2, void* __restrict__ C2,
    int mode, float scale0)
{
    const int z = blockIdx.z;
    const __half* W   = Wbase + ((size_t)z << 20);
    const float* bias = (z == 0) ? bb0 : (z == 1) ? bb1 : bb2;
    void* C           = (z == 0) ? C0  : (z == 1) ? C1  : C2;
    const float sc    = (z == 0) ? scale0 : 1.0f;

    __shared__ unsigned char gsm[2 * GSTG3 * GBUF];   // 48 KB

    const int tid  = threadIdx.x;
    const int warp = tid >> 5, lane = tid & 31;
    const int g = lane >> 2, l = lane & 3;
    const int wm = (warp >> 2) * 64;
    const int wn = (warp & 3) * 32;
    const int m0 = blockIdx.y * 128;
    const int n0 = blockIdx.x * 128;

    const int crow = tid >> 2;
    const int cch  = (tid & 3) * 8;
    const int sst  = (tid >> 3) & 3;
    const int cdst = crow * 64 + (((tid & 3) ^ sst) * 16);

    const int a_hi  = lane >> 4;
    const int sa    = ((lane & 15) >> 1) & 3;
    const int a_row = (wm + (lane & 15)) * 64;
    const int ac0   = ((0 + a_hi) ^ sa) * 16;
    const int ac1   = ((2 + a_hi) ^ sa) * 16;
    const int b_hi  = (lane >> 3) & 1;
    const int sb    = ((lane & 7) >> 1) & 3;
    const int b_row = (wn + (lane & 7)) * 64;
    const int bc0   = ((0 + b_hi) ^ sb) * 16;
    const int bc1   = ((2 + b_hi) ^ sb) * 16;

    const uint32_t sA0 = smaddr(gsm);
    const uint32_t sW0 = sA0 + GSTG3 * GBUF;

    const __half* Abase = A + (size_t)(m0 + crow) * D_ + cch;
    const __half* Wrow  = W + (size_t)(n0 + crow) * D_ + cch;

    float acc[4][4][4];
#pragma unroll
    for (int mi = 0; mi < 4; mi++)
#pragma unroll
        for (int ni = 0; ni < 4; ni++)
#pragma unroll
            for (int e = 0; e < 4; e++) acc[mi][ni][e] = 0.0f;

#pragma unroll
    for (int s = 0; s < 2; s++) {
        const __half* as = Abase + s * 32;
        const __half* ws = Wrow  + s * 32;
        cpasync16(sA0 + s * GBUF + cdst, as);
        cpasync16(sW0 + s * GBUF + cdst, ws);
        cpasync16(sA0 + s * GBUF + cdst + 4096, as + 64 * D_);
        cpasync16(sW0 + s * GBUF + cdst + 4096, ws + 64 * D_);
        asm volatile("cp.async.commit_group;");
    }

    int bc = 0;
    int nb = 2;
    for (int kt = 0; kt < 32; kt++) {
        asm volatile("cp.async.wait_group 1;");
        __syncthreads();

        const uint32_t aB = sA0 + bc * GBUF + a_row;
        const uint32_t bB = sW0 + bc * GBUF + b_row;

        unsigned af[4][4], bf[4][2];
#pragma unroll
        for (int mi = 0; mi < 4; mi++)
            ldsm_x4(af[mi], aB + mi * 1024 + ac0);
#pragma unroll
        for (int ni = 0; ni < 4; ni++)
            ldsm_x2(bf[ni], bB + ni * 512 + bc0);

        {
            const int nt = (kt + 2 < 32) ? (kt + 2) : 31;
            const __half* as = Abase + nt * 32;
            const __half* ws = Wrow  + nt * 32;
            cpasync16(sA0 + nb * GBUF + cdst, as);
            cpasync16(sW0 + nb * GBUF + cdst, ws);
            cpasync16(sA0 + nb * GBUF + cdst + 4096, as + 64 * D_);
            cpasync16(sW0 + nb * GBUF + cdst + 4096, ws + 64 * D_);
            asm volatile("cp.async.commit_group;");
        }

#pragma unroll
        for (int mi = 0; mi < 4; mi++)
#pragma unroll
            for (int ni = 0; ni < 4; ni++)
                mma_f16(acc[mi][ni], af[mi], bf[ni]);

#pragma unroll
        for (int mi = 0; mi < 4; mi++)
            ldsm_x4(af[mi], aB + mi * 1024 + ac1);
#pragma unroll
        for (int ni = 0; ni < 4; ni++)
            ldsm_x2(bf[ni], bB + ni * 512 + bc1);
#pragma unroll
        for (int mi = 0; mi < 4; mi++)
#pragma unroll
            for (int ni = 0; ni < 4; ni++)
                mma_f16(acc[mi][ni], af[mi], bf[ni]);

        bc++; if (bc == 3) bc = 0;
        nb++; if (nb == 3) nb = 0;
    }

    // epilogue
#pragma unroll
    for (int ni = 0; ni < 4; ni++) {
        int n = n0 + wn + ni * 8 + 2 * l;
        float bv0 = __ldg(bias + n);
        float bv1 = __ldg(bias + n + 1);
#pragma unroll
        for (int mi = 0; mi < 4; mi++) {
            int m = m0 + wm + mi * 16 + g;
#pragma unroll
            for (int half_ = 0; half_ < 2; half_++) {
                int mm = m + half_ * 8;
                float v0 = acc[mi][ni][half_ * 2 + 0] + bv0;
                float v1 = acc[mi][ni][half_ * 2 + 1] + bv1;
                if (mode == 0) {
                    float2 v; v.x = v0; v.y = v1;
                    *(float2*)((float*)C + (size_t)mm * D_ + n) = v;
                } else {
                    int bb = mm >> 11;
                    int t  = mm & (T_ - 1);
                    int hh = n >> 6;
                    int d  = n & (DH - 1);
                    unsigned hv = packh2(v0 * sc, v1 * sc);
                    *(unsigned*)((__half*)C + (((size_t)(bb * H_ + hh)) * T_ + t) * DH + d) = hv;
                }
            }
        }
    }
}

// ===========================================================================
// fp16 flash attention: BM=256 (16 warps, 512 threads), BN=64, dh=64.
// 2-stage cp.async pipeline, ONE sync/tile, x4 / x4.trans pair loads,
// all-ones mask fast path. Exp via ex2.approx.f16x2 (result IS the P
// fragment); row sums l computed as P @ ones on the tensor pipe (4 extra
// HMMA/tile) -- no scalar adds, no final quad reduction. Output fp16 [B,T,D].
// ===========================================================================
#define FBM 256
#define FBN 64
#define ATB (FBN*72*2)
#define ONESH2 0x3C003C00u   // half2(1.0, 1.0)

__global__ __launch_bounds__(512, 1) void attn_f16(
    const __half* __restrict__ Qh, const __half* __restrict__ Kh,
    const __half* __restrict__ Vh, const int* __restrict__ mask,
    __half* __restrict__ O)
{
    __shared__ __half Ks[2][FBN][72];
    __shared__ __half Vs[2][FBN][72];
    __shared__ int    Mall[T_];
    __shared__ int    Mflag[T_/FBN];

    const int bh = blockIdx.y;
    const int b  = bh >> 4;
    const int h  = bh & (H_ - 1);
    const int tid  = threadIdx.x;
    const int warp = tid >> 5, lane = tid & 31;
    const int g = lane >> 2, l = lane & 3;
    const int mrow0 = blockIdx.x * FBM + warp * 16;

    const __half* kb0 = Kh + (size_t)bh * T_ * DH;
    const __half* vb0 = Vh + (size_t)bh * T_ * DH;
    const uint32_t ks0 = smaddr(&Ks[0][0][0]);
    const uint32_t vs0 = smaddr(&Vs[0][0][0]);

    const int crow0 = tid >> 3;
    const int cc8   = (tid & 7) * 8;
    const int cdst  = crow0 * 144 + (tid & 7) * 16;

    {
        cpasync16(ks0 + cdst, kb0 + (size_t)crow0 * DH + cc8);
        cpasync16(vs0 + cdst, vb0 + (size_t)crow0 * DH + cc8);
        asm volatile("cp.async.commit_group;");
    }

    for (int i = tid; i < T_; i += 512) Mall[i] = mask[b * T_ + i];
    __syncthreads();
    if (tid < T_/FBN) {
        int f = 1;
        for (int j = 0; j < FBN; j++) f &= Mall[tid * FBN + j];
        Mflag[tid] = f;
    }

    unsigned qf[4][4];
    {
        const __half* qb = Qh + ((size_t)bh * T_ + mrow0) * DH;
#pragma unroll
        for (int kt = 0; kt < 4; kt++) {
            qf[kt][0] = *(const unsigned*)(qb + (size_t)g       * DH + kt*16 + 2*l);
            qf[kt][1] = *(const unsigned*)(qb + (size_t)(g + 8) * DH + kt*16 + 2*l);
            qf[kt][2] = *(const unsigned*)(qb + (size_t)g       * DH + kt*16 + 2*l + 8);
            qf[kt][3] = *(const unsigned*)(qb + (size_t)(g + 8) * DH + kt*16 + 2*l + 8);
        }
    }

    float oa[8][4];
#pragma unroll
    for (int ni = 0; ni < 8; ni++)
#pragma unroll
        for (int e = 0; e < 4; e++) oa[ni][e] = 0.0f;
    float m0 = -INFINITY, m1 = -INFINITY;
    float l0 = 0.0f, l1 = 0.0f;
    const unsigned bones[2] = { ONESH2, ONESH2 };

    const int q4 = lane >> 3;
    const int sq_base = ((lane & 7) + (q4 >> 1) * 8) * 144 + (q4 & 1) * 16;
    const int pv_base = ((q4 & 1) * 8 + (lane & 7)) * 144 + (q4 >> 1) * 16;

    for (int t = 0; t < 32; t++) {
        const int buf = t & 1;
        asm volatile("cp.async.wait_group 0;");
        __syncthreads();

        if (t < 31) {
            const int nb2 = buf ^ 1;
            cpasync16(ks0 + nb2 * ATB + cdst, kb0 + (size_t)((t + 1) * FBN + crow0) * DH + cc8);
            cpasync16(vs0 + nb2 * ATB + cdst, vb0 + (size_t)((t + 1) * FBN + crow0) * DH + cc8);
            asm volatile("cp.async.commit_group;");
        }

        // S = Q K^T
        float sa[8][4];
#pragma unroll
        for (int ni = 0; ni < 8; ni++)
#pragma unroll
            for (int e = 0; e < 4; e++) sa[ni][e] = 0.0f;
        const uint32_t kbase = ks0 + buf * ATB + sq_base;
#pragma unroll
        for (int kt = 0; kt < 4; kt++) {
#pragma unroll
            for (int np = 0; np < 4; np++) {
                unsigned b4[4];
                ldsm_x4(b4, kbase + np * 2304 + kt * 32);
                mma_f16(sa[2*np],     qf[kt], b4);
                mma_f16(sa[2*np + 1], qf[kt], b4 + 2);
            }
        }

        // mask (skipped when the whole 64-block is unmasked)
        if (!Mflag[t]) {
            const int mb = t * FBN;
#pragma unroll
            for (int ni = 0; ni < 8; ni++) {
                int c0m = Mall[mb + ni*8 + 2*l];
                int c1m = Mall[mb + ni*8 + 2*l + 1];
                if (!c0m) { sa[ni][0] = NEG_INF_F; sa[ni][2] = NEG_INF_F; }
                if (!c1m) { sa[ni][1] = NEG_INF_F; sa[ni][3] = NEG_INF_F; }
            }
        }

        float rm0 = -INFINITY, rm1 = -INFINITY;
#pragma unroll
        for (int ni = 0; ni < 8; ni++) {
            rm0 = fmaxf(rm0, fmaxf(sa[ni][0], sa[ni][1]));
            rm1 = fmaxf(rm1, fmaxf(sa[ni][2], sa[ni][3]));
        }
        rm0 = fmaxf(rm0, __shfl_xor_sync(0xffffffffu, rm0, 1));
        rm0 = fmaxf(rm0, __shfl_xor_sync(0xffffffffu, rm0, 2));
        rm1 = fmaxf(rm1, __shfl_xor_sync(0xffffffffu, rm1, 1));
        rm1 = fmaxf(rm1, __shfl_xor_sync(0xffffffffu, rm1, 2));
        float mn0 = fmaxf(m0, rm0);
        float mn1 = fmaxf(m1, rm1);
        float cr0 = ex2(m0 - mn0);
        float cr1 = ex2(m1 - mn1);

        // exp via packed f16x2 MUFU; result IS the P fragment
        unsigned pk[8][2];
#pragma unroll
        for (int ni = 0; ni < 8; ni++) {
            pk[ni][0] = h2ex2(sa[ni][0] - mn0, sa[ni][1] - mn0);
            pk[ni][1] = h2ex2(sa[ni][2] - mn1, sa[ni][3] - mn1);
        }
#pragma unroll
        for (int ni = 0; ni < 8; ni++) {
            oa[ni][0] *= cr0; oa[ni][1] *= cr0;
            oa[ni][2] *= cr1; oa[ni][3] *= cr1;
        }
        m0 = mn0; m1 = mn1;

        // O += P V; row sums ls = P @ ones on the tensor pipe
        float ls[4] = {0.0f, 0.0f, 0.0f, 0.0f};
        const uint32_t vbase = vs0 + buf * ATB + pv_base;
#pragma unroll
        for (int kt2 = 0; kt2 < 4; kt2++) {
            unsigned pa[4];
            pa[0] = pk[2*kt2][0];
            pa[1] = pk[2*kt2][1];
            pa[2] = pk[2*kt2 + 1][0];
            pa[3] = pk[2*kt2 + 1][1];
            mma_f16(ls, pa, bones);
#pragma unroll
            for (int np = 0; np < 4; np++) {
                unsigned b4[4];
                ldsm_x4t(b4, vbase + kt2 * 2304 + np * 32);
                mma_f16(oa[2*np],     pa, b4);
                mma_f16(oa[2*np + 1], pa, b4 + 2);
            }
        }
        l0 = l0 * cr0 + ls[0];
        l1 = l1 * cr1 + ls[2];
    }

    float i0 = 1.0f / l0;
    float i1 = 1.0f / l1;

    __half* ob = O + ((size_t)(b * T_ + mrow0)) * D_ + h * DH;
#pragma unroll
    for (int ni = 0; ni < 8; ni++) {
        unsigned v0 = packh2(oa[ni][0] * i0, oa[ni][1] * i0);
        unsigned v1 = packh2(oa[ni][2] * i1, oa[ni][3] * i1);
        *(unsigned*)(ob + (size_t)g       * D_ + ni*8 + 2*l) = v0;
        *(unsigned*)(ob + (size_t)(g + 8) * D_ + ni*8 + 2*l) = v1;
    }
}

// ===========================================================================
extern "C" void kernel_launch(void* const* d_in, const int* in_sizes, int n_in,
                              void* d_out, int out_size)
{
    (void)in_sizes; (void)n_in; (void)out_size;
    const float* x    = (const float*)d_in[0];
    const int*   mask = (const int*)  d_in[1];
    const float* Wq   = (const float*)d_in[2];
    const float* bq   = (const float*)d_in[3];
    const float* Wk   = (const float*)d_in[4];
    const float* bk   = (const float*)d_in[5];
    const float* Wv   = (const float*)d_in[6];
    const float* bv   = (const float*)d_in[7];
    const float* Wo   = (const float*)d_in[8];
    const float* bo   = (const float*)d_in[9];
    float* out = (float*)d_out;

    __half *q, *k, *v, *attn, *xh, *wh;
    cudaGetSymbolAddress((void**)&q,    g_qh);
    cudaGetSymbolAddress((void**)&k,    g_kh);
    cudaGetSymbolAddress((void**)&v,    g_vh);
    cudaGetSymbolAddress((void**)&attn, g_attn);
    cudaGetSymbolAddress((void**)&xh,   g_xh);
    cudaGetSymbolAddress((void**)&wh,   g_wh);

    convert_all<<<8192, 256>>>(x, Wq, Wk, Wv, Wo, xh, wh);

    mma_gemm_f16<<<dim3(D_/128, M_/128, 3), 256>>>(
        xh, wh, bq, q, bk, k, bv, v, 1, QSC);

    attn_f16<<<dim3(T_/FBM, B_*H_), 512>>>(q, k, v, mask, attn);

    mma_gemm_f16<<<dim3(D_/128, M_/128, 1), 256>>>(
        attn, wh + ((size_t)3 << 20), bo, out, bo, out, bo, out, 0, 1.0f);
}